// round 7
// baseline (speedup 1.0000x reference)
#include <cuda_runtime.h>
#include <cuda_bf16.h>

#define FEAT 128
#define NUM_GRAPHS 10000

// Segment boundary table: bounds[g] = first row index with batch[row] >= g.
// bounds[NUM_GRAPHS] = n_rows. Covers empty segments naturally.
__device__ int d_bounds[NUM_GRAPHS + 1];

// ---------------------------------------------------------------------------
// Kernel A: compute segment boundaries from the sorted batch array.
// Row i writes bounds[g] = i for every g in (batch[i-1], batch[i]].
// The last row also closes out the trailing segments.
// ---------------------------------------------------------------------------
__global__ void bounds_kernel(const int* __restrict__ batch, int n_rows) {
    int i = blockIdx.x * blockDim.x + threadIdx.x;
    if (i >= n_rows) return;
    int b    = batch[i];
    int prev = (i == 0) ? -1 : batch[i - 1];
    for (int g = prev + 1; g <= b; g++)
        d_bounds[g] = i;
    if (i == n_rows - 1) {
        for (int g = b + 1; g <= NUM_GRAPHS; g++)
            d_bounds[g] = n_rows;
    }
}

// ---------------------------------------------------------------------------
// Kernel B: one warp per output segment. Lane l owns feature columns
// [4l, 4l+4) as a float4. Stream the segment's contiguous rows with a
// 4-deep unrolled loop (4 independent LDG.128 in flight per warp), then a
// single plain STG.128 per lane. No atomics, no pre-zeroing, no index loads
// in the hot loop.
// ---------------------------------------------------------------------------
__global__ __launch_bounds__(128, 16) void segsum_kernel(
    const float4* __restrict__ hv,   // h_t as [n_rows][32] float4
    float4* __restrict__ out)        // [NUM_GRAPHS][32] float4
{
    const int warp = (blockIdx.x * blockDim.x + threadIdx.x) >> 5;
    const int lane = threadIdx.x & 31;
    if (warp >= NUM_GRAPHS) return;

    const int s = d_bounds[warp];       // warp-uniform, L2-resident (40 KB)
    const int e = d_bounds[warp + 1];

    const float4* p = hv + (long long)s * (FEAT / 4) + lane;
    const int n = e - s;

    float4 a0 = make_float4(0.f, 0.f, 0.f, 0.f);
    float4 a1 = a0, a2 = a0, a3 = a0;

    int i = 0;
    for (; i + 4 <= n; i += 4, p += 4 * (FEAT / 4)) {
        float4 v0 = p[0 * (FEAT / 4)];
        float4 v1 = p[1 * (FEAT / 4)];
        float4 v2 = p[2 * (FEAT / 4)];
        float4 v3 = p[3 * (FEAT / 4)];
        a0.x += v0.x; a0.y += v0.y; a0.z += v0.z; a0.w += v0.w;
        a1.x += v1.x; a1.y += v1.y; a1.z += v1.z; a1.w += v1.w;
        a2.x += v2.x; a2.y += v2.y; a2.z += v2.z; a2.w += v2.w;
        a3.x += v3.x; a3.y += v3.y; a3.z += v3.z; a3.w += v3.w;
    }
    for (; i < n; i++, p += (FEAT / 4)) {
        float4 v = p[0];
        a0.x += v.x; a0.y += v.y; a0.z += v.z; a0.w += v.w;
    }

    float4 r;
    r.x = (a0.x + a1.x) + (a2.x + a3.x);
    r.y = (a0.y + a1.y) + (a2.y + a3.y);
    r.z = (a0.z + a1.z) + (a2.z + a3.z);
    r.w = (a0.w + a1.w) + (a2.w + a3.w);

    out[(long long)warp * (FEAT / 4) + lane] = r;
}

// ---------------------------------------------------------------------------
// Harness entry point.
//   d_in[0] : h_t   float32 [N_NODES * FEAT]
//   d_in[1] : batch int32   [N_NODES]  (sorted)
//   d_out   : float32 [NUM_GRAPHS * FEAT]
// ---------------------------------------------------------------------------
extern "C" void kernel_launch(void* const* d_in, const int* in_sizes, int n_in,
                              void* d_out, int out_size) {
    const float4* hv    = (const float4*)d_in[0];
    const int*    batch = (const int*)d_in[1];
    float4*       out   = (float4*)d_out;
    const int n_rows = in_sizes[1];

    // A) Segment boundaries (also implicitly zeroes empty segments' ranges
    //    by making their bounds equal).
    bounds_kernel<<<(n_rows + 255) / 256, 256>>>(batch, n_rows);

    // B) One warp per segment: 10000 warps, 128-thread blocks -> 2500 blocks
    //    (fine-grained for load balance; 64 warps resident per SM).
    const int warps  = NUM_GRAPHS;
    const int blocks = (warps * 32 + 127) / 128;
    segsum_kernel<<<blocks, 128>>>(hv, out);
}

// round 8
// speedup vs baseline: 1.0338x; 1.0338x over previous
#include <cuda_runtime.h>
#include <cuda_bf16.h>

#define FEAT 128
#define NUM_GRAPHS 10000

// bounds[g] = first row index with batch[row] >= g; bounds[NUM_GRAPHS] = n_rows.
__device__ int d_bounds[NUM_GRAPHS + 1];

// ---------------------------------------------------------------------------
// Kernel A: segment boundaries from the sorted batch array + zero the output
// (harness poisons d_out; empty segments and atomic accumulation need zeros).
// ---------------------------------------------------------------------------
__global__ void bounds_zero_kernel(const int* __restrict__ batch, int n_rows,
                                   float4* __restrict__ out, int out4) {
    int i = blockIdx.x * blockDim.x + threadIdx.x;

    // Fused output zeroing (first 320K threads).
    if (i < out4) out[i] = make_float4(0.f, 0.f, 0.f, 0.f);

    if (i >= n_rows) return;
    int b    = batch[i];
    int prev = (i == 0) ? -1 : batch[i - 1];
    for (int g = prev + 1; g <= b; g++)
        d_bounds[g] = i;
    if (i == n_rows - 1) {
        for (int g = b + 1; g <= NUM_GRAPHS; g++)
            d_bounds[g] = n_rows;
    }
}

// ---------------------------------------------------------------------------
// Kernel B: balanced chunks + boundary-table streaming.
// Each warp owns a contiguous, equal-size row chunk (~61 rows). It splits the
// chunk into per-segment sub-streams using d_bounds (warp-uniform, L2-hot):
// each sub-stream is a branch-free 4-deep-unrolled LDG.128 loop into 4
// register float4 accumulators, flushed with 4 REDs. Avg ~2.6 flushes/warp.
// ---------------------------------------------------------------------------
__global__ __launch_bounds__(256, 8) void segsum_kernel(
    const float4* __restrict__ hv,     // h_t as [n_rows][32] float4
    const int* __restrict__ batch,     // sorted segment ids (only batch[s] read)
    float* __restrict__ out,           // [NUM_GRAPHS][FEAT]
    int n_rows)
{
    const int lane        = threadIdx.x & 31;
    const int gwarp       = (blockIdx.x * blockDim.x + threadIdx.x) >> 5;
    const int total_warps = (gridDim.x * blockDim.x) >> 5;

    int s = (int)(((long long)n_rows * gwarp) / total_warps);
    const int e = (int)(((long long)n_rows * (gwarp + 1)) / total_warps);
    if (s >= e) return;

    int g = batch[s];                       // segment of first owned row
    const float4* p = hv + (long long)s * (FEAT / 4) + lane;

    while (s < e) {
        const int lim = min(d_bounds[g + 1], e);
        const int n   = lim - s;

        float4 a0 = make_float4(0.f, 0.f, 0.f, 0.f);
        float4 a1 = a0, a2 = a0, a3 = a0;

        int i = 0;
        for (; i + 4 <= n; i += 4, p += 4 * (FEAT / 4)) {
            float4 v0 = p[0 * (FEAT / 4)];
            float4 v1 = p[1 * (FEAT / 4)];
            float4 v2 = p[2 * (FEAT / 4)];
            float4 v3 = p[3 * (FEAT / 4)];
            a0.x += v0.x; a0.y += v0.y; a0.z += v0.z; a0.w += v0.w;
            a1.x += v1.x; a1.y += v1.y; a1.z += v1.z; a1.w += v1.w;
            a2.x += v2.x; a2.y += v2.y; a2.z += v2.z; a2.w += v2.w;
            a3.x += v3.x; a3.y += v3.y; a3.z += v3.z; a3.w += v3.w;
        }
        for (; i < n; i++, p += (FEAT / 4)) {
            float4 v = p[0];
            a0.x += v.x; a0.y += v.y; a0.z += v.z; a0.w += v.w;
        }

        if (n > 0) {
            float4 r;
            r.x = (a0.x + a1.x) + (a2.x + a3.x);
            r.y = (a0.y + a1.y) + (a2.y + a3.y);
            r.z = (a0.z + a1.z) + (a2.z + a3.z);
            r.w = (a0.w + a1.w) + (a2.w + a3.w);
            float* o = out + (long long)g * FEAT + lane * 4;
            atomicAdd(o + 0, r.x);
            atomicAdd(o + 1, r.y);
            atomicAdd(o + 2, r.z);
            atomicAdd(o + 3, r.w);
        }

        s = lim;
        g++;
    }
}

// ---------------------------------------------------------------------------
// Harness entry point.
//   d_in[0] : h_t   float32 [N_NODES * FEAT]
//   d_in[1] : batch int32   [N_NODES]  (sorted)
//   d_out   : float32 [NUM_GRAPHS * FEAT]
// ---------------------------------------------------------------------------
extern "C" void kernel_launch(void* const* d_in, const int* in_sizes, int n_in,
                              void* d_out, int out_size) {
    const float4* hv    = (const float4*)d_in[0];
    const int*    batch = (const int*)d_in[1];
    float*        out   = (float*)d_out;
    const int n_rows = in_sizes[1];
    const int out4   = out_size / 4;

    // A) Boundaries + zero output (fused, one launch).
    bounds_zero_kernel<<<(n_rows + 255) / 256, 256>>>(batch, n_rows,
                                                      (float4*)d_out, out4);

    // B) Balanced segment sum: 2048 x 256 = 16384 warps, ~61 rows each.
    segsum_kernel<<<2048, 256>>>(hv, batch, out, n_rows);
}

// round 11
// speedup vs baseline: 1.3992x; 1.3534x over previous
#include <cuda_runtime.h>
#include <cuda_bf16.h>

#define FEAT 128
#define RV (FEAT / 4)          // 32 float4 per row
#define NUM_GRAPHS 10000

// ---------------------------------------------------------------------------
// Zero the output (harness poisons d_out with 0xAA; atomics need zeros).
// ---------------------------------------------------------------------------
__global__ void zero_kernel(float4* __restrict__ out, int n4) {
    int i = blockIdx.x * blockDim.x + threadIdx.x;
    if (i < n4) out[i] = make_float4(0.f, 0.f, 0.f, 0.f);
}

__device__ __forceinline__ void flush_seg(float* __restrict__ out, int g,
                                          int lane, const float4& a) {
    float* o = out + (long long)g * FEAT + lane * 4;
    atomicAdd(o + 0, a.x);
    atomicAdd(o + 1, a.y);
    atomicAdd(o + 2, a.z);
    atomicAdd(o + 3, a.w);
}

// ---------------------------------------------------------------------------
// Sorted segment-sum, balanced warp chunks, double-buffered 4-row blocks.
// Lane l owns features [4l,4l+4). While consuming block A (4 rows), block B's
// 4 LDG.128 are in flight -> steady MLP~4/warp with continuous issue.
// Per-row segment compare; REDs only at segment boundaries (~0.6/chunk).
// h_t read with __ldcs (use-once streaming, evict-first).
// ---------------------------------------------------------------------------
__global__ __launch_bounds__(256, 4) void segsum_kernel(
    const float4* __restrict__ hv,     // h_t as [n_rows][32] float4
    const int* __restrict__ batch,     // sorted segment ids
    float* __restrict__ out,           // [NUM_GRAPHS][FEAT]
    int n_rows)
{
    const int lane        = threadIdx.x & 31;
    const int gwarp       = (blockIdx.x * blockDim.x + threadIdx.x) >> 5;
    const int total_warps = (gridDim.x * blockDim.x) >> 5;

    int i = (int)(((long long)n_rows * gwarp) / total_warps);
    const int e = (int)(((long long)n_rows * (gwarp + 1)) / total_warps);
    if (i >= e) return;

    const float4* p = hv + (long long)i * RV + lane;
    int    cur = batch[i];
    float4 acc = make_float4(0.f, 0.f, 0.f, 0.f);

#define CONSUME(bb, vv)                                                  \
    do {                                                                 \
        if ((bb) != cur) {                                               \
            flush_seg(out, cur, lane, acc);                              \
            cur = (bb);                                                  \
            acc = (vv);                                                  \
        } else {                                                         \
            acc.x += (vv).x; acc.y += (vv).y;                            \
            acc.z += (vv).z; acc.w += (vv).w;                            \
        }                                                                \
    } while (0)

    if (e - i >= 4) {
        // Prime block A.
        float4 v0 = __ldcs(p + 0 * RV), v1 = __ldcs(p + 1 * RV);
        float4 v2 = __ldcs(p + 2 * RV), v3 = __ldcs(p + 3 * RV);
        int b0 = batch[i], b1 = batch[i + 1], b2 = batch[i + 2], b3 = batch[i + 3];

        while (e - i >= 8) {
            // Issue block B's loads before consuming block A.
            const float4* q = p + 4 * RV;
            float4 w0 = __ldcs(q + 0 * RV), w1 = __ldcs(q + 1 * RV);
            float4 w2 = __ldcs(q + 2 * RV), w3 = __ldcs(q + 3 * RV);
            int c0 = batch[i + 4], c1 = batch[i + 5];
            int c2 = batch[i + 6], c3 = batch[i + 7];

            CONSUME(b0, v0); CONSUME(b1, v1);
            CONSUME(b2, v2); CONSUME(b3, v3);

            v0 = w0; v1 = w1; v2 = w2; v3 = w3;
            b0 = c0; b1 = c1; b2 = c2; b3 = c3;
            p = q; i += 4;
        }
        // Consume the last primed block.
        CONSUME(b0, v0); CONSUME(b1, v1);
        CONSUME(b2, v2); CONSUME(b3, v3);
        p += 4 * RV; i += 4;
    }

    // Scalar tail (<4 rows).
    while (i < e) {
        float4 v = __ldcs(p);
        int    b = batch[i];
        CONSUME(b, v);
        p += RV; i++;
    }

    // Final flush (chunk may end mid-segment; neighbor shares it -> atomic).
    flush_seg(out, cur, lane, acc);
#undef CONSUME
}

// ---------------------------------------------------------------------------
// Harness entry point.
//   d_in[0] : h_t   float32 [N_NODES * FEAT]
//   d_in[1] : batch int32   [N_NODES]  (sorted)
//   d_out   : float32 [NUM_GRAPHS * FEAT]
// ---------------------------------------------------------------------------
extern "C" void kernel_launch(void* const* d_in, const int* in_sizes, int n_in,
                              void* d_out, int out_size) {
    const float4* hv    = (const float4*)d_in[0];
    const int*    batch = (const int*)d_in[1];
    float*        out   = (float*)d_out;
    const int n_rows = in_sizes[1];

    // 1) Zero the (poisoned) output.
    const int n4 = out_size / 4;
    zero_kernel<<<(n4 + 255) / 256, 256>>>((float4*)d_out, n4);

    // 2) Segment sum: 1776 blocks = 148 SMs x 4 blocks x 3 exact waves,
    //    14208 warps x ~70 rows each.
    segsum_kernel<<<1776, 256>>>(hv, batch, out, n_rows);
}